// round 11
// baseline (speedup 1.0000x reference)
#include <cuda_runtime.h>
#include <math.h>

#define NN 100000
#define NE 3200000
#define DF 128
#define HID 16
#define NC 2
#define WTP 132             // transposed-W row stride (floats); multiple of 4 (alignment),
                            // (132f+...)%32 = (4f+...)%32 -> c-lanes hit distinct banks

// ---------------- scratch (no allocations allowed) ----------------
__device__ float  g_deg[NN];
__device__ float  g_dinv[NN];
__device__ float4 g_h1s[NN * 4];   // (x@W1) * dinv
__device__ float4 g_acc1[NN * 4];  // layer-1 aggregate (init = self-loop term)
__device__ float2 g_h2s[NN];       // (relu@W2) * dinv
__device__ float2 g_acc2[NN];      // layer-2 aggregate

// ---------------- kernels ----------------

__global__ void k_init_deg() {
    int i = blockIdx.x * blockDim.x + threadIdx.x;
    if (i < NN) g_deg[i] = 1.0f;  // self-loop
}

__global__ void k_deg(const int* __restrict__ dst) {
    int e = blockIdx.x * blockDim.x + threadIdx.x;
    if (e < NE) atomicAdd(&g_deg[dst[e]], 1.0f);  // RED, no return
}

__global__ void k_dinv() {
    int i = blockIdx.x * blockDim.x + threadIdx.x;
    if (i < NN) g_dinv[i] = rsqrtf(g_deg[i]);  // deg >= 1 always
}

// ---------------- GEMM1: 4 lanes/node + TRANSPOSED W (conflict-free) --------
// Lane (n,c) loads x4[n*32 + k4*4 + c]: the 4 c-lanes of a node cover 64
// contiguous bytes -> 8 cache lines per warp LDG (vs 32 in R4).
// W stored transposed WT[f*132+k]; the float4 read WT[f*132 + k4*16 + c*4]
// starts at bank (4f+16k4+4c)%32: for fixed (f,k4) the 4 c-values give 4
// distinct float4s covering 16 distinct banks, 8-lane broadcast each ->
// conflict-free (R8's 4-way conflict came from the un-transposed 1024B stride).
// 12.5K warps total -> ~84 warps/SM of latency-hiding (vs 21 with 1 thr/node).
__global__ void __launch_bounds__(256) k_gemm1(const float* __restrict__ x,
                                               const float* __restrict__ W1) {
    __shared__ __align__(16) float WT[HID * WTP];  // 8.45 KB
    int tid = threadIdx.x;
    for (int i = tid; i < DF * HID; i += 256) {
        int k = i / HID, f = i % HID;      // W1[k][f]
        WT[f * WTP + k] = W1[i];           // one-time transpose (minor conflicts ok)
    }
    __syncthreads();

    int lane = tid & 31;
    int c = lane & 3;
    int node = blockIdx.x * 64 + (tid >> 2);
    if (node >= NN) return;                // NN % 8 == 0: whole warp exits together

    const float4* xrow = (const float4*)(x + (size_t)node * DF);
    float acc[HID];
#pragma unroll
    for (int f = 0; f < HID; f++) acc[f] = 0.0f;

#pragma unroll
    for (int k4 = 0; k4 < 8; k4++) {
        float4 xv = __ldg(&xrow[k4 * 4 + c]);          // 8 lines/warp-instr
        const float* wb = &WT[k4 * 16 + c * 4];        // + f*WTP
#pragma unroll
        for (int f = 0; f < HID; f++) {
            float4 w = *(const float4*)&wb[f * WTP];   // conflict-free broadcast
            acc[f] = fmaf(xv.x, w.x, acc[f]);
            acc[f] = fmaf(xv.y, w.y, acc[f]);
            acc[f] = fmaf(xv.z, w.z, acc[f]);
            acc[f] = fmaf(xv.w, w.w, acc[f]);
        }
    }

    // Reduce across the 4 c-lanes of this node (lane bits [0:1]).
#pragma unroll
    for (int f = 0; f < HID; f++) {
        acc[f] += __shfl_xor_sync(0xffffffffu, acc[f], 1);
        acc[f] += __shfl_xor_sync(0xffffffffu, acc[f], 2);
    }

    float di = g_dinv[node];
    float4 o;
    o.x = acc[c * 4 + 0] * di;
    o.y = acc[c * 4 + 1] * di;
    o.z = acc[c * 4 + 2] * di;
    o.w = acc[c * 4 + 3] * di;
    g_h1s[node * 4 + c] = o;               // lanes -> consecutive float4s: coalesced
    g_acc1[node * 4 + c] = o;              // self-loop init
}

// ---- layer-1 scatter: 4 threads/edge, one v4 RED each (R4, proven) ----
__global__ void k_scatter1(const int* __restrict__ src, const int* __restrict__ dst) {
    int t = blockIdx.x * blockDim.x + threadIdx.x;
    if (t >= NE * 4) return;
    int e = t >> 2;
    int c = t & 3;
    int s = src[e];
    int d = dst[e];
    float4 v = g_h1s[s * 4 + c];
    float4* p = &g_acc1[d * 4 + c];
    asm volatile("red.global.add.v4.f32 [%0], {%1, %2, %3, %4};"
                 :: "l"(p), "f"(v.x), "f"(v.y), "f"(v.z), "f"(v.w)
                 : "memory");
}

// Per node: finish layer1 (scale + bias + relu), apply W2, pre-scale for layer2.
__global__ void k_finish1(const float* __restrict__ b1, const float* __restrict__ W2) {
    int i = blockIdx.x * blockDim.x + threadIdx.x;
    if (i >= NN) return;
    float di = g_dinv[i];
    float z0 = 0.0f, z1 = 0.0f;
#pragma unroll
    for (int q = 0; q < 4; q++) {
        float4 a = g_acc1[i * 4 + q];
        float av[4] = {a.x, a.y, a.z, a.w};
#pragma unroll
        for (int j = 0; j < 4; j++) {
            int f = q * 4 + j;
            float v = fmaxf(fmaf(di, av[j], __ldg(&b1[f])), 0.0f);
            z0 = fmaf(v, __ldg(&W2[f * NC + 0]), z0);
            z1 = fmaf(v, __ldg(&W2[f * NC + 1]), z1);
        }
    }
    float2 h;
    h.x = z0 * di;
    h.y = z1 * di;
    g_h2s[i] = h;
    g_acc2[i] = h;  // self-loop init
}

// ---- layer-2 scatter: 1 thread/edge, 1 v2 RED (R4, proven) ----
__global__ void k_scatter2(const int* __restrict__ src, const int* __restrict__ dst) {
    int e = blockIdx.x * blockDim.x + threadIdx.x;
    if (e >= NE) return;
    int s = src[e];
    int d = dst[e];
    float2 v = g_h2s[s];
    float2* p = &g_acc2[d];
    asm volatile("red.global.add.v2.f32 [%0], {%1, %2};"
                 :: "l"(p), "f"(v.x), "f"(v.y) : "memory");
}

// Finish layer 2 + log_softmax (2 classes).
__global__ void k_final(const float* __restrict__ b2, float* __restrict__ out) {
    int i = blockIdx.x * blockDim.x + threadIdx.x;
    if (i >= NN) return;
    float di = g_dinv[i];
    float2 a = g_acc2[i];
    float z0 = fmaf(di, a.x, __ldg(&b2[0]));
    float z1 = fmaf(di, a.y, __ldg(&b2[1]));
    float m = fmaxf(z0, z1);
    float lse = m + logf(expf(z0 - m) + expf(z1 - m));
    float2 o;
    o.x = z0 - lse;
    o.y = z1 - lse;
    ((float2*)out)[i] = o;
}

// ---------------- launch ----------------

extern "C" void kernel_launch(void* const* d_in, const int* in_sizes, int n_in,
                              void* d_out, int out_size) {
    const float* x = 0; const float* W1 = 0; const float* b1 = 0;
    const float* W2 = 0; const float* b2 = 0; const int* ei = 0;
    for (int i = 0; i < n_in; i++) {
        long long s = in_sizes[i];
        if (s == (long long)NN * DF)      x  = (const float*)d_in[i];
        else if (s == DF * HID)           W1 = (const float*)d_in[i];
        else if (s == HID)                b1 = (const float*)d_in[i];
        else if (s == HID * NC)           W2 = (const float*)d_in[i];
        else if (s == NC)                 b2 = (const float*)d_in[i];
        else if (s == 2LL * NE)           ei = (const int*)d_in[i];
    }
    const int* src = ei;        // row 0
    const int* dst = ei + NE;   // row 1

    const int T = 256;
    const int NBn = (NN + T - 1) / T;
    const int NBe = (NE + T - 1) / T;

    k_init_deg<<<NBn, T>>>();
    k_deg<<<NBe, T>>>(dst);
    k_dinv<<<NBn, T>>>();
    k_gemm1<<<(NN + 63) / 64, 256>>>(x, W1);
    k_scatter1<<<(NE * 4 + T - 1) / T, T>>>(src, dst);
    k_finish1<<<NBn, T>>>(b1, W2);
    k_scatter2<<<NBe, T>>>(src, dst);
    k_final<<<NBn, T>>>(b2, (float*)d_out);
}

// round 12
// speedup vs baseline: 1.0306x; 1.0306x over previous
#include <cuda_runtime.h>
#include <math.h>

#define NN 100000
#define NE 3200000
#define DF 128
#define HID 16
#define NC 2
#define GB 256              // nodes (and threads) per gemm block
#define XP 33               // XS row stride (odd): conflict-free
#define KC 32               // k-chunk size
#define GEMM_BLKS 391       // ceil(NN/GB)
#define DEG_BLKS 205
#define FUSED_BLKS (GEMM_BLKS + DEG_BLKS)

// ---------------- scratch (no allocations allowed) ----------------
__device__ float  g_deg[NN];
__device__ float  g_dinv[NN];
__device__ float4 g_h1s[NN * 4];   // raw x@W1, then scaled in k_scale
__device__ float4 g_acc1[NN * 4];  // layer-1 aggregate (init = self-loop term)
__device__ float2 g_h2s[NN];       // (relu@W2) * dinv
__device__ float2 g_acc2[NN];      // layer-2 aggregate

// ---------------- kernels ----------------

__global__ void k_init_deg() {
    int i = blockIdx.x * blockDim.x + threadIdx.x;
    if (i < NN) g_deg[i] = 1.0f;  // self-loop
}

// ---- FUSED: blocks [0,391) = gemm1 (R10 structure, raw output);
//      blocks [391,596) = degree REDs. Independent work, disjoint pipes
//      (FMA/LDS vs LTS/REDG), all 596 blocks co-resident -> true overlap.
__global__ void __launch_bounds__(GB) k_fused(const float* __restrict__ x,
                                              const float* __restrict__ W1,
                                              const int* __restrict__ dst) {
    __shared__ __align__(16) float W1s[DF * HID];  // 8 KB
    __shared__ float XS[GB * XP];                  // 33.8 KB
    int tid = threadIdx.x;

    if (blockIdx.x >= GEMM_BLKS) {
        // ---- degree path: grid-stride REDs ----
        int b = blockIdx.x - GEMM_BLKS;
        for (int e = b * GB + tid; e < NE; e += DEG_BLKS * GB)
            atomicAdd(&g_deg[dst[e]], 1.0f);  // RED, no return
        return;
    }

    // ---- gemm path (R10 chunked, conflict-free; no dinv here) ----
    int base = blockIdx.x * GB;
    int nb = NN - base; if (nb > GB) nb = GB;

    for (int i = tid; i < DF * HID; i += GB) W1s[i] = W1[i];

    float acc[HID];
#pragma unroll
    for (int f = 0; f < HID; f++) acc[f] = 0.0f;

    for (int ch = 0; ch < DF / KC; ch++) {
        __syncthreads();
        for (int i = tid; i < nb * (KC / 4); i += GB) {
            int n = i >> 3, j4 = i & 7;
            float4 v = *(const float4*)(x + (size_t)(base + n) * DF + ch * KC + j4 * 4);
            float* p = &XS[n * XP + j4 * 4];
            p[0] = v.x; p[1] = v.y; p[2] = v.z; p[3] = v.w;
        }
        __syncthreads();

        if (tid < nb) {
            const float* xr = &XS[tid * XP];
#pragma unroll
            for (int kk = 0; kk < KC; kk++) {
                float xs = xr[kk];
                const float4* wr = (const float4*)&W1s[(ch * KC + kk) * HID];
#pragma unroll
                for (int q = 0; q < 4; q++) {
                    float4 w = wr[q];
                    acc[q * 4 + 0] = fmaf(xs, w.x, acc[q * 4 + 0]);
                    acc[q * 4 + 1] = fmaf(xs, w.y, acc[q * 4 + 1]);
                    acc[q * 4 + 2] = fmaf(xs, w.z, acc[q * 4 + 2]);
                    acc[q * 4 + 3] = fmaf(xs, w.w, acc[q * 4 + 3]);
                }
            }
        }
    }

    if (tid >= nb) return;
    int node = base + tid;
#pragma unroll
    for (int q = 0; q < 4; q++) {
        float4 v;
        v.x = acc[q * 4 + 0];
        v.y = acc[q * 4 + 1];
        v.z = acc[q * 4 + 2];
        v.w = acc[q * 4 + 3];
        g_h1s[node * 4 + q] = v;  // raw; scaled in k_scale
    }
}

// dinv = rsqrt(deg); h1s *= dinv; acc1 = scaled value (self-loop init).
__global__ void k_scale() {
    int i = blockIdx.x * blockDim.x + threadIdx.x;
    if (i >= NN) return;
    float di = rsqrtf(g_deg[i]);  // deg >= 1 always
    g_dinv[i] = di;
#pragma unroll
    for (int q = 0; q < 4; q++) {
        float4 v = g_h1s[i * 4 + q];
        v.x *= di; v.y *= di; v.z *= di; v.w *= di;
        g_h1s[i * 4 + q] = v;
        g_acc1[i * 4 + q] = v;
    }
}

// ---- layer-1 scatter: 4 threads/edge, one v4 RED each (proven) ----
__global__ void k_scatter1(const int* __restrict__ src, const int* __restrict__ dst) {
    int t = blockIdx.x * blockDim.x + threadIdx.x;
    if (t >= NE * 4) return;
    int e = t >> 2;
    int c = t & 3;
    int s = src[e];
    int d = dst[e];
    float4 v = g_h1s[s * 4 + c];
    float4* p = &g_acc1[d * 4 + c];
    asm volatile("red.global.add.v4.f32 [%0], {%1, %2, %3, %4};"
                 :: "l"(p), "f"(v.x), "f"(v.y), "f"(v.z), "f"(v.w)
                 : "memory");
}

// Per node: finish layer1 (scale + bias + relu), apply W2, pre-scale for layer2.
__global__ void k_finish1(const float* __restrict__ b1, const float* __restrict__ W2) {
    int i = blockIdx.x * blockDim.x + threadIdx.x;
    if (i >= NN) return;
    float di = g_dinv[i];
    float z0 = 0.0f, z1 = 0.0f;
#pragma unroll
    for (int q = 0; q < 4; q++) {
        float4 a = g_acc1[i * 4 + q];
        float av[4] = {a.x, a.y, a.z, a.w};
#pragma unroll
        for (int j = 0; j < 4; j++) {
            int f = q * 4 + j;
            float v = fmaxf(fmaf(di, av[j], __ldg(&b1[f])), 0.0f);
            z0 = fmaf(v, __ldg(&W2[f * NC + 0]), z0);
            z1 = fmaf(v, __ldg(&W2[f * NC + 1]), z1);
        }
    }
    float2 h;
    h.x = z0 * di;
    h.y = z1 * di;
    g_h2s[i] = h;
    g_acc2[i] = h;  // self-loop init
}

// ---- layer-2 scatter: 1 thread/edge, 1 v2 RED (proven) ----
__global__ void k_scatter2(const int* __restrict__ src, const int* __restrict__ dst) {
    int e = blockIdx.x * blockDim.x + threadIdx.x;
    if (e >= NE) return;
    int s = src[e];
    int d = dst[e];
    float2 v = g_h2s[s];
    float2* p = &g_acc2[d];
    asm volatile("red.global.add.v2.f32 [%0], {%1, %2};"
                 :: "l"(p), "f"(v.x), "f"(v.y) : "memory");
}

// Finish layer 2 + log_softmax (2 classes).
__global__ void k_final(const float* __restrict__ b2, float* __restrict__ out) {
    int i = blockIdx.x * blockDim.x + threadIdx.x;
    if (i >= NN) return;
    float di = g_dinv[i];
    float2 a = g_acc2[i];
    float z0 = fmaf(di, a.x, __ldg(&b2[0]));
    float z1 = fmaf(di, a.y, __ldg(&b2[1]));
    float m = fmaxf(z0, z1);
    float lse = m + logf(expf(z0 - m) + expf(z1 - m));
    float2 o;
    o.x = z0 - lse;
    o.y = z1 - lse;
    ((float2*)out)[i] = o;
}

// ---------------- launch ----------------

extern "C" void kernel_launch(void* const* d_in, const int* in_sizes, int n_in,
                              void* d_out, int out_size) {
    const float* x = 0; const float* W1 = 0; const float* b1 = 0;
    const float* W2 = 0; const float* b2 = 0; const int* ei = 0;
    for (int i = 0; i < n_in; i++) {
        long long s = in_sizes[i];
        if (s == (long long)NN * DF)      x  = (const float*)d_in[i];
        else if (s == DF * HID)           W1 = (const float*)d_in[i];
        else if (s == HID)                b1 = (const float*)d_in[i];
        else if (s == HID * NC)           W2 = (const float*)d_in[i];
        else if (s == NC)                 b2 = (const float*)d_in[i];
        else if (s == 2LL * NE)           ei = (const int*)d_in[i];
    }
    const int* src = ei;        // row 0
    const int* dst = ei + NE;   // row 1

    const int T = 256;
    const int NBn = (NN + T - 1) / T;
    const int NBe = (NE + T - 1) / T;

    k_init_deg<<<NBn, T>>>();
    k_fused<<<FUSED_BLKS, GB>>>(x, W1, dst);   // gemm1 || degree REDs
    k_scale<<<NBn, T>>>();
    k_scatter1<<<(NE * 4 + T - 1) / T, T>>>(src, dst);
    k_finish1<<<NBn, T>>>(b1, W2);
    k_scatter2<<<NBe, T>>>(src, dst);
    k_final<<<NBn, T>>>(b2, (float*)d_out);
}

// round 13
// speedup vs baseline: 1.0459x; 1.0149x over previous
#include <cuda_runtime.h>
#include <cuda_fp16.h>
#include <math.h>

#define NN 100000
#define NE 3200000
#define DF 128
#define HID 16
#define NC 2
#define GB 256              // nodes (and threads) per gemm block
#define XP 33               // XS row stride (odd): conflict-free
#define KC 32               // k-chunk size
#define GEMM_BLKS 391       // ceil(NN/GB)
#define DEG_BLKS 205
#define FUSED_BLKS (GEMM_BLKS + DEG_BLKS)

// ---------------- scratch (no allocations allowed) ----------------
__device__ float    g_deg[NN];
__device__ float    g_dinv[NN];
__device__ float4   g_h1s[NN * 4];   // raw x@W1 (fp32, gemm output)
__device__ uint2    g_h1h[NN * 4];   // scaled h1 packed as 4x half2 per uint2; 32B/node
__device__ float4   g_acc1[NN * 4];  // layer-1 aggregate, fp32 (init = exact self-loop)
__device__ unsigned g_h2h[NN];       // scaled h2 packed as half2
__device__ float2   g_acc2[NN];      // layer-2 aggregate, fp32

union HU { __half2 h; unsigned u; };

// ---------------- kernels ----------------

__global__ void k_init_deg() {
    int i = blockIdx.x * blockDim.x + threadIdx.x;
    if (i < NN) g_deg[i] = 1.0f;  // self-loop
}

// ---- FUSED: blocks [0,391) = gemm1 (raw output); blocks [391,596) = degree REDs.
__global__ void __launch_bounds__(GB) k_fused(const float* __restrict__ x,
                                              const float* __restrict__ W1,
                                              const int* __restrict__ dst) {
    __shared__ __align__(16) float W1s[DF * HID];  // 8 KB
    __shared__ float XS[GB * XP];                  // 33.8 KB
    int tid = threadIdx.x;

    if (blockIdx.x >= GEMM_BLKS) {
        int b = blockIdx.x - GEMM_BLKS;
        for (int e = b * GB + tid; e < NE; e += DEG_BLKS * GB)
            atomicAdd(&g_deg[dst[e]], 1.0f);  // RED, no return
        return;
    }

    int base = blockIdx.x * GB;
    int nb = NN - base; if (nb > GB) nb = GB;

    for (int i = tid; i < DF * HID; i += GB) W1s[i] = W1[i];

    float acc[HID];
#pragma unroll
    for (int f = 0; f < HID; f++) acc[f] = 0.0f;

    for (int ch = 0; ch < DF / KC; ch++) {
        __syncthreads();
        for (int i = tid; i < nb * (KC / 4); i += GB) {
            int n = i >> 3, j4 = i & 7;
            float4 v = *(const float4*)(x + (size_t)(base + n) * DF + ch * KC + j4 * 4);
            float* p = &XS[n * XP + j4 * 4];
            p[0] = v.x; p[1] = v.y; p[2] = v.z; p[3] = v.w;
        }
        __syncthreads();

        if (tid < nb) {
            const float* xr = &XS[tid * XP];
#pragma unroll
            for (int kk = 0; kk < KC; kk++) {
                float xs = xr[kk];
                const float4* wr = (const float4*)&W1s[(ch * KC + kk) * HID];
#pragma unroll
                for (int q = 0; q < 4; q++) {
                    float4 w = wr[q];
                    acc[q * 4 + 0] = fmaf(xs, w.x, acc[q * 4 + 0]);
                    acc[q * 4 + 1] = fmaf(xs, w.y, acc[q * 4 + 1]);
                    acc[q * 4 + 2] = fmaf(xs, w.z, acc[q * 4 + 2]);
                    acc[q * 4 + 3] = fmaf(xs, w.w, acc[q * 4 + 3]);
                }
            }
        }
    }

    if (tid >= nb) return;
    int node = base + tid;
#pragma unroll
    for (int q = 0; q < 4; q++) {
        float4 v;
        v.x = acc[q * 4 + 0];
        v.y = acc[q * 4 + 1];
        v.z = acc[q * 4 + 2];
        v.w = acc[q * 4 + 3];
        g_h1s[node * 4 + q] = v;  // raw fp32
    }
}

// dinv = rsqrt(deg); acc1 = h1*dinv (exact fp32 self-loop init);
// h1h = fp16-packed h1*dinv (scatter payload).
__global__ void k_scale() {
    int i = blockIdx.x * blockDim.x + threadIdx.x;
    if (i >= NN) return;
    float di = rsqrtf(g_deg[i]);  // deg >= 1 always
    g_dinv[i] = di;
#pragma unroll
    for (int q = 0; q < 4; q++) {
        float4 v = g_h1s[i * 4 + q];
        v.x *= di; v.y *= di; v.z *= di; v.w *= di;
        g_acc1[i * 4 + q] = v;            // exact self-loop term
        HU a, b;
        a.h = __floats2half2_rn(v.x, v.y);
        b.h = __floats2half2_rn(v.z, v.w);
        g_h1h[i * 4 + q] = make_uint2(a.u, b.u);
    }
}

// ---- layer-1 scatter: 4 threads/edge; fp16 gather (8B/lane, one 32B sector
//      per edge for the whole node row), fp32 v4 RED accumulate.
__global__ void k_scatter1(const int* __restrict__ src, const int* __restrict__ dst) {
    int t = blockIdx.x * blockDim.x + threadIdx.x;
    if (t >= NE * 4) return;
    int e = t >> 2;
    int c = t & 3;
    int s = src[e];
    int d = dst[e];
    uint2 u = g_h1h[s * 4 + c];
    HU a, b; a.u = u.x; b.u = u.y;
    float2 f0 = __half22float2(a.h);
    float2 f1 = __half22float2(b.h);
    float4* p = &g_acc1[d * 4 + c];
    asm volatile("red.global.add.v4.f32 [%0], {%1, %2, %3, %4};"
                 :: "l"(p), "f"(f0.x), "f"(f0.y), "f"(f1.x), "f"(f1.y)
                 : "memory");
}

// Per node: finish layer1 (scale + bias + relu), apply W2, pre-scale for layer2.
__global__ void k_finish1(const float* __restrict__ b1, const float* __restrict__ W2) {
    int i = blockIdx.x * blockDim.x + threadIdx.x;
    if (i >= NN) return;
    float di = g_dinv[i];
    float z0 = 0.0f, z1 = 0.0f;
#pragma unroll
    for (int q = 0; q < 4; q++) {
        float4 a = g_acc1[i * 4 + q];
        float av[4] = {a.x, a.y, a.z, a.w};
#pragma unroll
        for (int j = 0; j < 4; j++) {
            int f = q * 4 + j;
            float v = fmaxf(fmaf(di, av[j], __ldg(&b1[f])), 0.0f);
            z0 = fmaf(v, __ldg(&W2[f * NC + 0]), z0);
            z1 = fmaf(v, __ldg(&W2[f * NC + 1]), z1);
        }
    }
    float2 h;
    h.x = z0 * di;
    h.y = z1 * di;
    g_acc2[i] = h;                    // exact fp32 self-loop term
    HU p; p.h = __floats2half2_rn(h.x, h.y);
    g_h2h[i] = p.u;                   // fp16 scatter payload
}

// ---- layer-2 scatter: fp16 gather (4B), fp32 v2 RED ----
__global__ void k_scatter2(const int* __restrict__ src, const int* __restrict__ dst) {
    int e = blockIdx.x * blockDim.x + threadIdx.x;
    if (e >= NE) return;
    int s = src[e];
    int d = dst[e];
    HU p; p.u = g_h2h[s];
    float2 v = __half22float2(p.h);
    float2* q = &g_acc2[d];
    asm volatile("red.global.add.v2.f32 [%0], {%1, %2};"
                 :: "l"(q), "f"(v.x), "f"(v.y) : "memory");
}

// Finish layer 2 + log_softmax (2 classes).
__global__ void k_final(const float* __restrict__ b2, float* __restrict__ out) {
    int i = blockIdx.x * blockDim.x + threadIdx.x;
    if (i >= NN) return;
    float di = g_dinv[i];
    float2 a = g_acc2[i];
    float z0 = fmaf(di, a.x, __ldg(&b2[0]));
    float z1 = fmaf(di, a.y, __ldg(&b2[1]));
    float m = fmaxf(z0, z1);
    float lse = m + logf(expf(z0 - m) + expf(z1 - m));
    float2 o;
    o.x = z0 - lse;
    o.y = z1 - lse;
    ((float2*)out)[i] = o;
}

// ---------------- launch ----------------

extern "C" void kernel_launch(void* const* d_in, const int* in_sizes, int n_in,
                              void* d_out, int out_size) {
    const float* x = 0; const float* W1 = 0; const float* b1 = 0;
    const float* W2 = 0; const float* b2 = 0; const int* ei = 0;
    for (int i = 0; i < n_in; i++) {
        long long s = in_sizes[i];
        if (s == (long long)NN * DF)      x  = (const float*)d_in[i];
        else if (s == DF * HID)           W1 = (const float*)d_in[i];
        else if (s == HID)                b1 = (const float*)d_in[i];
        else if (s == HID * NC)           W2 = (const float*)d_in[i];
        else if (s == NC)                 b2 = (const float*)d_in[i];
        else if (s == 2LL * NE)           ei = (const int*)d_in[i];
    }
    const int* src = ei;        // row 0
    const int* dst = ei + NE;   // row 1

    const int T = 256;
    const int NBn = (NN + T - 1) / T;
    const int NBe = (NE + T - 1) / T;

    k_init_deg<<<NBn, T>>>();
    k_fused<<<FUSED_BLKS, GB>>>(x, W1, dst);   // gemm1 || degree REDs
    k_scale<<<NBn, T>>>();
    k_scatter1<<<(NE * 4 + T - 1) / T, T>>>(src, dst);
    k_finish1<<<NBn, T>>>(b1, W2);
    k_scatter2<<<NBe, T>>>(src, dst);
    k_final<<<NBn, T>>>(b2, (float*)d_out);
}

// round 15
// speedup vs baseline: 1.1874x; 1.1353x over previous
#include <cuda_runtime.h>
#include <cuda_fp16.h>
#include <math.h>

#define NN 100000
#define NE 3200000
#define DF 128
#define HID 16
#define NC 2
#define GB 256              // nodes (and threads) per gemm block
#define XP 33               // XS row stride (odd): conflict-free
#define KC 32               // k-chunk size
#define GEMM_BLKS 391       // ceil(NN/GB)
#define DEG_BLKS 205
#define FUSED_BLKS (GEMM_BLKS + DEG_BLKS)

// ---------------- scratch (no allocations allowed) ----------------
__device__ float    g_deg[NN];
__device__ float    g_dinv[NN];
__device__ float4   g_h1s[NN * 4];   // raw x@W1 (fp32, gemm output)
__device__ uint4    g_h1h[NN * 2];   // scaled h1 as 16 halfs (2x uint4) per node
__device__ uint4    g_acc1h[NN * 2]; // layer-1 aggregate in fp16 (8 halfs per uint4)
__device__ unsigned g_h2h[NN];       // scaled h2 packed as half2
__device__ float2   g_acc2[NN];      // layer-2 aggregate, fp32

union HU { __half2 h; unsigned u; };

// ---------------- kernels ----------------

__global__ void k_init_deg() {
    int i = blockIdx.x * blockDim.x + threadIdx.x;
    if (i < NN) g_deg[i] = 1.0f;  // self-loop
}

// ---- FUSED: blocks [0,391) = gemm1 (raw output); blocks [391,596) = degree REDs.
__global__ void __launch_bounds__(GB) k_fused(const float* __restrict__ x,
                                              const float* __restrict__ W1,
                                              const int* __restrict__ dst) {
    __shared__ __align__(16) float W1s[DF * HID];  // 8 KB
    __shared__ float XS[GB * XP];                  // 33.8 KB
    int tid = threadIdx.x;

    if (blockIdx.x >= GEMM_BLKS) {
        int b = blockIdx.x - GEMM_BLKS;
        for (int e = b * GB + tid; e < NE; e += DEG_BLKS * GB)
            atomicAdd(&g_deg[dst[e]], 1.0f);  // RED, no return
        return;
    }

    int base = blockIdx.x * GB;
    int nb = NN - base; if (nb > GB) nb = GB;

    for (int i = tid; i < DF * HID; i += GB) W1s[i] = W1[i];

    float acc[HID];
#pragma unroll
    for (int f = 0; f < HID; f++) acc[f] = 0.0f;

    for (int ch = 0; ch < DF / KC; ch++) {
        __syncthreads();
        for (int i = tid; i < nb * (KC / 4); i += GB) {
            int n = i >> 3, j4 = i & 7;
            float4 v = *(const float4*)(x + (size_t)(base + n) * DF + ch * KC + j4 * 4);
            float* p = &XS[n * XP + j4 * 4];
            p[0] = v.x; p[1] = v.y; p[2] = v.z; p[3] = v.w;
        }
        __syncthreads();

        if (tid < nb) {
            const float* xr = &XS[tid * XP];
#pragma unroll
            for (int kk = 0; kk < KC; kk++) {
                float xs = xr[kk];
                const float4* wr = (const float4*)&W1s[(ch * KC + kk) * HID];
#pragma unroll
                for (int q = 0; q < 4; q++) {
                    float4 w = wr[q];
                    acc[q * 4 + 0] = fmaf(xs, w.x, acc[q * 4 + 0]);
                    acc[q * 4 + 1] = fmaf(xs, w.y, acc[q * 4 + 1]);
                    acc[q * 4 + 2] = fmaf(xs, w.z, acc[q * 4 + 2]);
                    acc[q * 4 + 3] = fmaf(xs, w.w, acc[q * 4 + 3]);
                }
            }
        }
    }

    if (tid >= nb) return;
    int node = base + tid;
#pragma unroll
    for (int q = 0; q < 4; q++) {
        float4 v;
        v.x = acc[q * 4 + 0];
        v.y = acc[q * 4 + 1];
        v.z = acc[q * 4 + 2];
        v.w = acc[q * 4 + 3];
        g_h1s[node * 4 + q] = v;  // raw fp32
    }
}

// dinv = rsqrt(deg); h1h = fp16-packed h1*dinv; acc1h init = same (self-loop,
// one fp16 rounding — negligible vs accumulation noise).
__global__ void k_scale() {
    int i = blockIdx.x * blockDim.x + threadIdx.x;
    if (i >= NN) return;
    float di = rsqrtf(g_deg[i]);  // deg >= 1 always
    g_dinv[i] = di;
#pragma unroll
    for (int q = 0; q < 2; q++) {
        float4 a = g_h1s[i * 4 + q * 2 + 0];
        float4 b = g_h1s[i * 4 + q * 2 + 1];
        HU p0, p1, p2, p3;
        p0.h = __floats2half2_rn(a.x * di, a.y * di);
        p1.h = __floats2half2_rn(a.z * di, a.w * di);
        p2.h = __floats2half2_rn(b.x * di, b.y * di);
        p3.h = __floats2half2_rn(b.z * di, b.w * di);
        uint4 u = make_uint4(p0.u, p1.u, p2.u, p3.u);
        g_h1h[i * 2 + q] = u;
        g_acc1h[i * 2 + q] = u;   // self-loop init
    }
}

// ---- layer-1 scatter: 2 threads/edge; each gathers one uint4 (8 halfs) and
//      issues one red.global.add.noftz.v4.f16x2 (16B). Per edge: 2 RED lanes,
//      32B — half the lanes AND half the bytes of the fp32 version.
__global__ void k_scatter1(const int* __restrict__ src, const int* __restrict__ dst) {
    int t = blockIdx.x * blockDim.x + threadIdx.x;
    if (t >= NE * 2) return;
    int e = t >> 1;
    int c = t & 1;
    int s = src[e];
    int d = dst[e];
    uint4 u = g_h1h[s * 2 + c];
    uint4* p = &g_acc1h[d * 2 + c];
    asm volatile("red.global.add.noftz.v4.f16x2 [%0], {%1, %2, %3, %4};"
                 :: "l"(p), "r"(u.x), "r"(u.y), "r"(u.z), "r"(u.w)
                 : "memory");
}

// Per node: finish layer1 (scale + bias + relu), apply W2, pre-scale for layer2.
__global__ void k_finish1(const float* __restrict__ b1, const float* __restrict__ W2) {
    int i = blockIdx.x * blockDim.x + threadIdx.x;
    if (i >= NN) return;
    float di = g_dinv[i];
    float z0 = 0.0f, z1 = 0.0f;
#pragma unroll
    for (int q = 0; q < 2; q++) {
        uint4 u = g_acc1h[i * 2 + q];
        unsigned uu[4] = {u.x, u.y, u.z, u.w};
#pragma unroll
        for (int j = 0; j < 4; j++) {
            HU p; p.u = uu[j];
            float2 fv = __half22float2(p.h);
            int f = q * 8 + j * 2;
            float v0 = fmaxf(fmaf(di, fv.x, __ldg(&b1[f + 0])), 0.0f);
            float v1 = fmaxf(fmaf(di, fv.y, __ldg(&b1[f + 1])), 0.0f);
            z0 = fmaf(v0, __ldg(&W2[(f + 0) * NC + 0]), z0);
            z1 = fmaf(v0, __ldg(&W2[(f + 0) * NC + 1]), z1);
            z0 = fmaf(v1, __ldg(&W2[(f + 1) * NC + 0]), z0);
            z1 = fmaf(v1, __ldg(&W2[(f + 1) * NC + 1]), z1);
        }
    }
    float2 h;
    h.x = z0 * di;
    h.y = z1 * di;
    g_acc2[i] = h;                    // exact fp32 self-loop term
    HU p; p.h = __floats2half2_rn(h.x, h.y);
    g_h2h[i] = p.u;                   // fp16 scatter payload
}

// ---- layer-2 scatter: fp16 gather (4B), fp32 v2 RED (precision kept) ----
__global__ void k_scatter2(const int* __restrict__ src, const int* __restrict__ dst) {
    int e = blockIdx.x * blockDim.x + threadIdx.x;
    if (e >= NE) return;
    int s = src[e];
    int d = dst[e];
    HU p; p.u = g_h2h[s];
    float2 v = __half22float2(p.h);
    float2* q = &g_acc2[d];
    asm volatile("red.global.add.v2.f32 [%0], {%1, %2};"
                 :: "l"(q), "f"(v.x), "f"(v.y) : "memory");
}

// Finish layer 2 + log_softmax (2 classes).
__global__ void k_final(const float* __restrict__ b2, float* __restrict__ out) {
    int i = blockIdx.x * blockDim.x + threadIdx.x;
    if (i >= NN) return;
    float di = g_dinv[i];
    float2 a = g_acc2[i];
    float z0 = fmaf(di, a.x, __ldg(&b2[0]));
    float z1 = fmaf(di, a.y, __ldg(&b2[1]));
    float m = fmaxf(z0, z1);
    float lse = m + logf(expf(z0 - m) + expf(z1 - m));
    float2 o;
    o.x = z0 - lse;
    o.y = z1 - lse;
    ((float2*)out)[i] = o;
}

// ---------------- launch ----------------

extern "C" void kernel_launch(void* const* d_in, const int* in_sizes, int n_in,
                              void* d_out, int out_size) {
    const float* x = 0; const float* W1 = 0; const float* b1 = 0;
    const float* W2 = 0; const float* b2 = 0; const int* ei = 0;
    for (int i = 0; i < n_in; i++) {
        long long s = in_sizes[i];
        if (s == (long long)NN * DF)      x  = (const float*)d_in[i];
        else if (s == DF * HID)           W1 = (const float*)d_in[i];
        else if (s == HID)                b1 = (const float*)d_in[i];
        else if (s == HID * NC)           W2 = (const float*)d_in[i];
        else if (s == NC)                 b2 = (const float*)d_in[i];
        else if (s == 2LL * NE)           ei = (const int*)d_in[i];
    }
    const int* src = ei;        // row 0
    const int* dst = ei + NE;   // row 1

    const int T = 256;
    const int NBn = (NN + T - 1) / T;
    const int NBe = (NE + T - 1) / T;

    k_init_deg<<<NBn, T>>>();
    k_fused<<<FUSED_BLKS, GB>>>(x, W1, dst);   // gemm1 || degree REDs
    k_scale<<<NBn, T>>>();
    k_scatter1<<<(NE * 2 + T - 1) / T, T>>>(src, dst);
    k_finish1<<<NBn, T>>>(b1, W2);
    k_scatter2<<<NBe, T>>>(src, dst);
    k_final<<<NBn, T>>>(b2, (float*)d_out);
}